// round 13
// baseline (speedup 1.0000x reference)
#include <cuda_runtime.h>
#include <cstdint>

static constexpr int   T_LEN = 4096;
static constexpr int   TC    = 64;            // steps per chunk
static constexpr int   NCH   = T_LEN / TC;    // 64
static constexpr int   ROWS  = 32;            // rows per block
static constexpr int   XD    = 5;             // x-tile ring depth (span k-2..k+2)
static constexpr int   VD    = 2;             // v buffer ring depth
static constexpr int   SD    = 4;             // spike-bit ring depth (span k-3..k)
static constexpr int   STRW  = 68;            // padded words/row (bank-safe, 16B-aligned)
static constexpr float VTH   = 1.27f;

// Coalesced chunk copy-issue: lane (q2=lane>>4, m2=lane&15) covers row 2r+q2,
// bytes 16*m2, r=0..15. Each warp-op = 2 rows x 256B = 4 full lines.
// Does NOT commit — caller commits (possibly empty) groups so wait_group
// depth accounting stays exact on the tail (round-8 invariant).
__device__ __forceinline__ void cp_chunk_issue(const float* gchunk, float* stile,
                                               int q2, int m2)
{
#pragma unroll
    for (int r = 0; r < 16; ++r) {
        const int rr = 2 * r + q2;
        unsigned sa = (unsigned)__cvta_generic_to_shared(stile + rr * STRW + 4 * m2);
        asm volatile("cp.async.ca.shared.global [%0], [%1], 16;\n"
                     :: "r"(sa), "l"(gchunk + (size_t)rr * T_LEN + 4 * m2));
    }
}

__device__ __forceinline__ void cp_commit()
{
    asm volatile("cp.async.commit_group;\n");
}

__global__ void __launch_bounds__(128)
lif_fused(const float* __restrict__ ode, const float* __restrict__ decay_p,
          float* __restrict__ v_out, float* __restrict__ s_out,
          float* __restrict__ dv_out)
{
    __shared__ float    xt[XD][ROWS][STRW];   // input chunks (ring)
    __shared__ float    vb[VD][ROWS][STRW];   // v values (ring)
    __shared__ unsigned sb[SD][ROWS][2];      // spike bits per chunk (2 words)
    __shared__ unsigned Wsh[ROWS][2];         // dv zero-window per row (2 words)

    const int wid  = threadIdx.x >> 5;
    const int lane = threadIdx.x & 31;
    const int q2   = lane >> 4;               // 0..1 : row parity group
    const int m2   = lane & 15;               // 0..15: 16B segment in chunk
    const int row0 = blockIdx.x * ROWS;
    const float dec = __ldg(decay_p);
    const float* xg0 = ode + (size_t)row0 * T_LEN;

    // scan state (w0): aa = pre-clamp value of previous step,
    // s1..s5 = spike masks (~0 iff spike) for steps t-1..t-5.
    float aa = 0.0f;
    int s1 = 0, s2 = 0, s3 = 0, s4 = 0, s5 = 0;

    if (wid == 1) {
        cp_chunk_issue(xg0 + 0 * TC, &xt[0][0][0], q2, m2); cp_commit();
        cp_chunk_issue(xg0 + 1 * TC, &xt[1][0][0], q2, m2); cp_commit();
        asm volatile("cp.async.wait_group 1;\n" ::: "memory");  // chunk 0 ready
    }
    __syncthreads();

    for (int k = 0; k < NCH + 2; ++k) {
        // ---------------- w0: scan chunk k (lane = row) ----------------
        if (wid == 0 && k < NCH) {
            const float* xr = &xt[k % XD][lane][0];
            float*       vr = &vb[k % VD][lane][0];
            unsigned bits0 = 0u, bits1 = 0u;
            if (k == 0) {
                // general machine over the whole first chunk (t=0 edge exact)
                float v = 0.0f, t2 = 0.0f; int c = 0, z = 0; bool s = false;
#pragma unroll 4
                for (int t = 0; t < TC; ++t) {
                    float x  = xr[t];
                    float xe = (z > 0) ? 0.0f : x;
                    float vd = fmaf(-dec, v, v);
                    float a  = vd + xe;
                    float b  = (c == 1) ? xe : a;
                    t2 = (c >= 2) ? VTH : b;
                    s  = t2 > VTH;
                    v  = fminf(t2, VTH);
                    vr[t] = v;
                    if (t < 32) bits0 |= s ? (1u << t) : 0u;
                    else        bits1 |= s ? (1u << (t - 32)) : 0u;
                    c = s ? (c + 1) : (c > 0 ? c - 1 : 0);
                    z = s ? (t > 0 ? 5 : z) : (z > 0 ? z - 1 : 0);
                }
                aa = t2;
                s1 = (int)bits1 >> 31;
                s2 = (int)(bits1 << 1) >> 31;
                s3 = (int)(bits1 << 2) >> 31;
                s4 = (int)(bits1 << 3) >> 31;
                s5 = (int)(bits1 << 4) >> 31;
            } else {
#pragma unroll
                for (int half = 0; half < 2; ++half) {
                    // hoist half-chunk into registers: LDS latency off the chain
                    float4 xv[8];
#pragma unroll
                    for (int g4 = 0; g4 < 8; ++g4)
                        xv[g4] = *reinterpret_cast<const float4*>(xr + 32 * half + 4 * g4);
                    unsigned bits = 0u;
#pragma unroll
                    for (int g4 = 0; g4 < 8; ++g4) {
                        float xs[4] = {xv[g4].x, xv[g4].y, xv[g4].z, xv[g4].w};
                        float vs[4];
#pragma unroll
                        for (int qq = 0; qq < 4; ++qq) {
                            const int t = 4 * g4 + qq;
                            int w1m = s2 | s3 | s4;
                            int xm  = __float_as_int(xs[qq]) & ~(w1m | s5);
                            float vd  = fmaf(-dec, aa, aa);
                            float sum = vd + __int_as_float(xm);
                            float aan = __int_as_float(__float_as_int(sum) & ~s1);
                            int   sm  = __float_as_int(VTH - aan) >> 31;
                            vs[qq] = fminf(aan, VTH);
                            bits |= (1u << t) & (unsigned)sm;
                            s5 = s4; s4 = s3; s3 = s2; s2 = s1; s1 = sm;
                            aa = aan;
                        }
                        *reinterpret_cast<float4*>(vr + 32 * half + 4 * g4) =
                            make_float4(vs[0], vs[1], vs[2], vs[3]);
                    }
                    if (half == 0) bits0 = bits; else bits1 = bits;
                }
            }
            sb[k % SD][lane][0] = bits0;
            sb[k % SD][lane][1] = bits1;
        }

        // ------ w1: prefetch + coalesced v store (chunk k-1) ------
        if (wid == 1) {
            if (k + 2 < NCH)
                cp_chunk_issue(xg0 + (size_t)(k + 2) * TC, &xt[(k + 2) % XD][0][0], q2, m2);
            cp_commit();   // ALWAYS commit (empty on tail) — keeps wait_group
                           // depth exact so chunk k+1 is provably complete
            const int c = k - 1;
            if (c >= 0 && c < NCH) {
                const float* vbb = &vb[c % VD][0][0];
                float* vout = v_out + (size_t)row0 * T_LEN + (size_t)c * TC;
#pragma unroll
                for (int r = 0; r < 16; ++r) {
                    const int rr = 2 * r + q2;
                    float4 v4 = *reinterpret_cast<const float4*>(vbb + rr * STRW + 4 * m2);
                    *reinterpret_cast<float4*>(vout + (size_t)rr * T_LEN + 4 * m2) = v4;
                }
            }
            asm volatile("cp.async.wait_group 1;\n" ::: "memory");
        }

        // ------ w2: coalesced s store (chunk k-1) ------
        if (wid == 2) {
            const int c = k - 1;
            if (c >= 0 && c < NCH) {
                float* sout = s_out + (size_t)row0 * T_LEN + (size_t)c * TC;
                const int h  = m2 >> 3;            // bit word for this segment
                const int tb = 4 * (m2 & 7);       // bit base within word
#pragma unroll
                for (int r = 0; r < 16; ++r) {
                    const int rr = 2 * r + q2;
                    const unsigned msk = sb[c % SD][rr][h];
                    float sf[4];
#pragma unroll
                    for (int j = 0; j < 4; ++j)
                        sf[j] = __int_as_float(
                            ((int)(msk << (31 - (tb + j))) >> 31) & 0x3f800000);
                    *reinterpret_cast<float4*>(sout + (size_t)rr * T_LEN + 4 * m2) =
                        make_float4(sf[0], sf[1], sf[2], sf[3]);
                }
            }
        }

        // ------ w3: coalesced dv (chunk k-2) ------
        if (wid == 3) {
            const int c = k - 2;
            if (c >= 0 && c < NCH) {
                // phase A: lane computes zero-window words for its own row
                const unsigned* sbc = sb[c % SD][lane];
#pragma unroll
                for (int h = 0; h < 2; ++h) {
                    unsigned mm, mp, mn;
                    if (h == 0) {
                        mm = sbc[0];
                        mp = (c > 0) ? sb[(c - 1) % SD][lane][1] : 0u;
                        mn = sbc[1] & 1u;
                        if (c == 0) mm &= ~1u;   // spike at t=0 zeroes nothing
                    } else {
                        mm = sbc[1];
                        mp = sbc[0];
                        if (c == 0) mp &= ~1u;
                        mn = (c + 1 < NCH) ? (sb[(c + 1) % SD][lane][0] & 1u) : 0u;
                    }
                    unsigned long long W = ((unsigned long long)mm << 5) | (mp >> 27)
                                         | ((unsigned long long)mn << 37);
                    W |= W >> 1; W |= W >> 2; W |= W >> 3;
                    Wsh[lane][h] = (unsigned)W;  // bit t set -> zero dv[..+32h+t]
                }
                __syncwarp();
                // phase B: coalesced store pass
                const float* xb = &xt[c % XD][0][0];
                float* dout = dv_out + (size_t)row0 * T_LEN + (size_t)c * TC;
                const int h  = m2 >> 3;
                const int tb = 4 * (m2 & 7);
#pragma unroll
                for (int r = 0; r < 16; ++r) {
                    const int rr = 2 * r + q2;
                    const unsigned V = Wsh[rr][h];
                    float4 x4 = *reinterpret_cast<const float4*>(xb + rr * STRW + 4 * m2);
                    int xw[4] = {__float_as_int(x4.x), __float_as_int(x4.y),
                                 __float_as_int(x4.z), __float_as_int(x4.w)};
                    float rv[4];
#pragma unroll
                    for (int j = 0; j < 4; ++j) {
                        int mskb = (int)(V << (31 - (tb + j))) >> 31;
                        rv[j] = __int_as_float(xw[j] & ~mskb);
                    }
                    *reinterpret_cast<float4*>(dout + (size_t)rr * T_LEN + 4 * m2) =
                        make_float4(rv[0], rv[1], rv[2], rv[3]);
                }
                __syncwarp();   // protect Wsh before next iteration's phase A
            }
        }

        __syncthreads();
    }
}

extern "C" void kernel_launch(void* const* d_in, const int* in_sizes, int n_in,
                              void* d_out, int out_size)
{
    const float* ode     = (const float*)d_in[0];
    const float* decay_p = (const float*)d_in[1];
    float*       out     = (float*)d_out;

    const int BT = in_sizes[0];
    const int B  = BT / T_LEN;

    float* v_out  = out;
    float* s_out  = out + (size_t)BT;
    float* dv_out = out + (size_t)2 * BT;

    lif_fused<<<B / ROWS, 128>>>(ode, decay_p, v_out, s_out, dv_out);
}

// round 14
// speedup vs baseline: 1.1518x; 1.1518x over previous
#include <cuda_runtime.h>
#include <cstdint>

static constexpr int   T_LEN = 4096;
static constexpr int   TC    = 64;            // steps per chunk
static constexpr int   NCH   = T_LEN / TC;    // 64
static constexpr int   ROWS  = 32;            // rows per block
static constexpr int   XD    = 5;             // x-tile ring depth (span k-2..k+2)
static constexpr int   VD    = 2;             // v buffer ring depth
static constexpr int   SD    = 4;             // spike-bit ring depth (span k-3..k)
static constexpr int   STRW  = 68;            // padded words/row (bank-safe, 16B-aligned)
static constexpr float VTH   = 1.27f;

// Coalesced chunk copy-issue: lane (q2=lane>>4, m2=lane&15) covers row 2r+q2,
// bytes 16*m2, r=0..15. Each warp-op = 2 rows x 256B = 4 full lines.
// Does NOT commit — caller commits (possibly empty) groups so wait_group
// depth accounting stays exact on the tail (round-8 invariant).
__device__ __forceinline__ void cp_chunk_issue(const float* gchunk, float* stile,
                                               int q2, int m2)
{
#pragma unroll
    for (int r = 0; r < 16; ++r) {
        const int rr = 2 * r + q2;
        unsigned sa = (unsigned)__cvta_generic_to_shared(stile + rr * STRW + 4 * m2);
        asm volatile("cp.async.ca.shared.global [%0], [%1], 16;\n"
                     :: "r"(sa), "l"(gchunk + (size_t)rr * T_LEN + 4 * m2));
    }
}

__device__ __forceinline__ void cp_commit()
{
    asm volatile("cp.async.commit_group;\n");
}

__global__ void __launch_bounds__(128)
lif_fused(const float* __restrict__ ode, const float* __restrict__ decay_p,
          float* __restrict__ v_out, float* __restrict__ s_out,
          float* __restrict__ dv_out)
{
    __shared__ float    xt[XD][ROWS][STRW];   // input chunks (ring)
    __shared__ float    vb[VD][ROWS][STRW];   // RAW aan values (ring; w1 clamps)
    __shared__ unsigned sb[SD][ROWS][2];      // spike bits per chunk (2 words)
    __shared__ unsigned Wsh[ROWS][2];         // dv zero-window per row (2 words)

    const int wid  = threadIdx.x >> 5;
    const int lane = threadIdx.x & 31;
    const int q2   = lane >> 4;               // 0..1 : row parity group
    const int m2   = lane & 15;               // 0..15: 16B segment in chunk
    const int row0 = blockIdx.x * ROWS;
    const float dec = __ldg(decay_p);
    const float* xg0 = ode + (size_t)row0 * T_LEN;

    // scan state (w0): aa = pre-clamp value of previous step,
    // s1..s5 = spike masks (~0 iff spike) for steps t-1..t-5.
    float aa = 0.0f;
    int s1 = 0, s2 = 0, s3 = 0, s4 = 0, s5 = 0;

    if (wid == 1) {
        cp_chunk_issue(xg0 + 0 * TC, &xt[0][0][0], q2, m2); cp_commit();
        cp_chunk_issue(xg0 + 1 * TC, &xt[1][0][0], q2, m2); cp_commit();
        asm volatile("cp.async.wait_group 1;\n" ::: "memory");  // chunk 0 ready
    }
    __syncthreads();

    for (int k = 0; k < NCH + 2; ++k) {
        // ---------------- w0: scan chunk k (lane = row) ----------------
        if (wid == 0 && k < NCH) {
            const float* xr = &xt[k % XD][lane][0];
            float*       vr = &vb[k % VD][lane][0];
            unsigned bits0 = 0u, bits1 = 0u;
            if (k == 0) {
                // general machine over whole first chunk (t=0 edge exact);
                // stores RAW pre-clamp value (w1 clamps with fminf later)
                float v = 0.0f, t2 = 0.0f; int c = 0, z = 0; bool s = false;
#pragma unroll 4
                for (int t = 0; t < TC; ++t) {
                    float x  = xr[t];
                    float xe = (z > 0) ? 0.0f : x;
                    float vd = fmaf(-dec, v, v);
                    float a  = vd + xe;
                    float b  = (c == 1) ? xe : a;
                    t2 = (c >= 2) ? VTH : b;
                    s  = t2 > VTH;
                    v  = fminf(t2, VTH);
                    vr[t] = t2;                       // raw; clamp deferred to w1
                    if (t < 32) bits0 |= s ? (1u << t) : 0u;
                    else        bits1 |= s ? (1u << (t - 32)) : 0u;
                    c = s ? (c + 1) : (c > 0 ? c - 1 : 0);
                    z = s ? (t > 0 ? 5 : z) : (z > 0 ? z - 1 : 0);
                }
                aa = t2;
                s1 = (int)bits1 >> 31;
                s2 = (int)(bits1 << 1) >> 31;
                s3 = (int)(bits1 << 2) >> 31;
                s4 = (int)(bits1 << 3) >> 31;
                s5 = (int)(bits1 << 4) >> 31;
            } else {
                // rolling 2-group prefetch: group g+1 LDS in flight while
                // group g scans (~56 cy ahead >> 29 cy LDS latency)
                float4 xc = *reinterpret_cast<const float4*>(xr);
#pragma unroll
                for (int g4 = 0; g4 < 16; ++g4) {
                    float4 xn;
                    if (g4 + 1 < 16)
                        xn = *reinterpret_cast<const float4*>(xr + 4 * (g4 + 1));
                    float xs[4] = {xc.x, xc.y, xc.z, xc.w};
                    float4 vs4;
                    float vs[4];
#pragma unroll
                    for (int qq = 0; qq < 4; ++qq) {
                        int w1m = s2 | s3 | s4;
                        int xm  = __float_as_int(xs[qq]) & ~(w1m | s5);
                        float vd  = fmaf(-dec, aa, aa);
                        float sum = vd + __int_as_float(xm);
                        float aan = __int_as_float(__float_as_int(sum) & ~s1);
                        int   sm  = __float_as_int(VTH - aan) >> 31;
                        vs[qq] = aan;                 // raw; clamp deferred to w1
                        const int t = 4 * g4 + qq;
                        if (t < 32) bits0 |= (1u << t) & (unsigned)sm;
                        else        bits1 |= (1u << (t - 32)) & (unsigned)sm;
                        s5 = s4; s4 = s3; s3 = s2; s2 = s1; s1 = sm;
                        aa = aan;
                    }
                    vs4 = make_float4(vs[0], vs[1], vs[2], vs[3]);
                    *reinterpret_cast<float4*>(vr + 4 * g4) = vs4;
                    xc = xn;
                }
            }
            sb[k % SD][lane][0] = bits0;
            sb[k % SD][lane][1] = bits1;
        }

        // ------ w1: prefetch + clamp + coalesced v store (chunk k-1) ------
        if (wid == 1) {
            if (k + 2 < NCH)
                cp_chunk_issue(xg0 + (size_t)(k + 2) * TC, &xt[(k + 2) % XD][0][0], q2, m2);
            cp_commit();   // ALWAYS commit (empty on tail) — keeps wait_group
                           // depth exact so chunk k+1 is provably complete
            const int c = k - 1;
            if (c >= 0 && c < NCH) {
                const float* vbb = &vb[c % VD][0][0];
                float* vout = v_out + (size_t)row0 * T_LEN + (size_t)c * TC;
#pragma unroll
                for (int r = 0; r < 16; ++r) {
                    const int rr = 2 * r + q2;
                    float4 v4 = *reinterpret_cast<const float4*>(vbb + rr * STRW + 4 * m2);
                    v4.x = fminf(v4.x, VTH);
                    v4.y = fminf(v4.y, VTH);
                    v4.z = fminf(v4.z, VTH);
                    v4.w = fminf(v4.w, VTH);
                    *reinterpret_cast<float4*>(vout + (size_t)rr * T_LEN + 4 * m2) = v4;
                }
            }
            asm volatile("cp.async.wait_group 1;\n" ::: "memory");
        }

        // ------ w2: coalesced s store (chunk k-1) ------
        if (wid == 2) {
            const int c = k - 1;
            if (c >= 0 && c < NCH) {
                float* sout = s_out + (size_t)row0 * T_LEN + (size_t)c * TC;
                const int h  = m2 >> 3;            // bit word for this segment
                const int tb = 4 * (m2 & 7);       // bit base within word
#pragma unroll
                for (int r = 0; r < 16; ++r) {
                    const int rr = 2 * r + q2;
                    const unsigned msk = sb[c % SD][rr][h];
                    float sf[4];
#pragma unroll
                    for (int j = 0; j < 4; ++j)
                        sf[j] = __int_as_float(
                            ((int)(msk << (31 - (tb + j))) >> 31) & 0x3f800000);
                    *reinterpret_cast<float4*>(sout + (size_t)rr * T_LEN + 4 * m2) =
                        make_float4(sf[0], sf[1], sf[2], sf[3]);
                }
            }
        }

        // ------ w3: coalesced dv (chunk k-2) ------
        if (wid == 3) {
            const int c = k - 2;
            if (c >= 0 && c < NCH) {
                // phase A: lane computes zero-window words for its own row
                const unsigned* sbc = sb[c % SD][lane];
#pragma unroll
                for (int h = 0; h < 2; ++h) {
                    unsigned mm, mp, mn;
                    if (h == 0) {
                        mm = sbc[0];
                        mp = (c > 0) ? sb[(c - 1) % SD][lane][1] : 0u;
                        mn = sbc[1] & 1u;
                        if (c == 0) mm &= ~1u;   // spike at t=0 zeroes nothing
                    } else {
                        mm = sbc[1];
                        mp = sbc[0];
                        if (c == 0) mp &= ~1u;
                        mn = (c + 1 < NCH) ? (sb[(c + 1) % SD][lane][0] & 1u) : 0u;
                    }
                    unsigned long long W = ((unsigned long long)mm << 5) | (mp >> 27)
                                         | ((unsigned long long)mn << 37);
                    W |= W >> 1; W |= W >> 2; W |= W >> 3;
                    Wsh[lane][h] = (unsigned)W;  // bit t set -> zero dv[..+32h+t]
                }
                __syncwarp();
                // phase B: coalesced store pass
                const float* xb = &xt[c % XD][0][0];
                float* dout = dv_out + (size_t)row0 * T_LEN + (size_t)c * TC;
                const int h  = m2 >> 3;
                const int tb = 4 * (m2 & 7);
#pragma unroll
                for (int r = 0; r < 16; ++r) {
                    const int rr = 2 * r + q2;
                    const unsigned V = Wsh[rr][h];
                    float4 x4 = *reinterpret_cast<const float4*>(xb + rr * STRW + 4 * m2);
                    int xw[4] = {__float_as_int(x4.x), __float_as_int(x4.y),
                                 __float_as_int(x4.z), __float_as_int(x4.w)};
                    float rv[4];
#pragma unroll
                    for (int j = 0; j < 4; ++j) {
                        int mskb = (int)(V << (31 - (tb + j))) >> 31;
                        rv[j] = __int_as_float(xw[j] & ~mskb);
                    }
                    *reinterpret_cast<float4*>(dout + (size_t)rr * T_LEN + 4 * m2) =
                        make_float4(rv[0], rv[1], rv[2], rv[3]);
                }
                __syncwarp();   // protect Wsh before next iteration's phase A
            }
        }

        __syncthreads();
    }
}

extern "C" void kernel_launch(void* const* d_in, const int* in_sizes, int n_in,
                              void* d_out, int out_size)
{
    const float* ode     = (const float*)d_in[0];
    const float* decay_p = (const float*)d_in[1];
    float*       out     = (float*)d_out;

    const int BT = in_sizes[0];
    const int B  = BT / T_LEN;

    float* v_out  = out;
    float* s_out  = out + (size_t)BT;
    float* dv_out = out + (size_t)2 * BT;

    lif_fused<<<B / ROWS, 128>>>(ode, decay_p, v_out, s_out, dv_out);
}